// round 1
// baseline (speedup 1.0000x reference)
#include <cuda_runtime.h>
#include <math.h>

// Problem constants (dataset is fixed; window_size input == 512)
#define S_LEN 8192
#define DIM   1024
#define NH    16
#define HD    64
#define WIN   512

// Scratch activations (allocation-free rule: __device__ globals)
__device__ float g_q[S_LEN * DIM];
__device__ float g_k[S_LEN * DIM];
__device__ float g_v[S_LEN * DIM];
__device__ float g_o[S_LEN * DIM];

// ---------------------------------------------------------------------------
// SGEMM (NT): C[m,n] = sum_k A[m,k] * B[n,k]   (torch Linear: y = x @ W^T)
// 128x128 tile, BK=16, 256 threads, 8x8 per thread. Optional fused RoPE
// epilogue (interleaved-pair rotary on head-dim-64 columns).
// blockIdx.z selects (B, C, rope) so QKV runs as one launch.
// ---------------------------------------------------------------------------
#define BM 128
#define BN 128
#define BK 16

__global__ void __launch_bounds__(256) sgemm_nt(
    const float* __restrict__ A,
    const float* __restrict__ B0, const float* __restrict__ B1, const float* __restrict__ B2,
    float* __restrict__ C0, float* __restrict__ C1, float* __restrict__ C2,
    int rope_mask)
{
    const int z = blockIdx.z;
    const float* Bm = (z == 0) ? B0 : (z == 1) ? B1 : B2;
    float* C = (z == 0) ? C0 : (z == 1) ? C1 : C2;
    const bool rope = (rope_mask >> z) & 1;

    const int K = DIM;
    __shared__ float As[BK][BM];
    __shared__ float Bs[BK][BN];

    const int tid = threadIdx.x;
    const int tx = tid & 15;
    const int ty = tid >> 4;
    const int m0 = blockIdx.y * BM;
    const int n0 = blockIdx.x * BN;

    float acc[8][8];
#pragma unroll
    for (int i = 0; i < 8; i++)
#pragma unroll
        for (int j = 0; j < 8; j++) acc[i][j] = 0.f;

    const int lr = tid >> 2;          // 0..63
    const int lc = (tid & 3) << 2;    // 0,4,8,12

    const float* Aptr = A + (m0 + lr) * K + lc;
    const float* Bptr = Bm + (n0 + lr) * K + lc;

    for (int k0 = 0; k0 < K; k0 += BK) {
#pragma unroll
        for (int p = 0; p < 2; p++) {
            float4 va = *(const float4*)(Aptr + (size_t)p * 64 * K + k0);
            As[lc + 0][lr + p * 64] = va.x;
            As[lc + 1][lr + p * 64] = va.y;
            As[lc + 2][lr + p * 64] = va.z;
            As[lc + 3][lr + p * 64] = va.w;
            float4 vb = *(const float4*)(Bptr + (size_t)p * 64 * K + k0);
            Bs[lc + 0][lr + p * 64] = vb.x;
            Bs[lc + 1][lr + p * 64] = vb.y;
            Bs[lc + 2][lr + p * 64] = vb.z;
            Bs[lc + 3][lr + p * 64] = vb.w;
        }
        __syncthreads();
#pragma unroll
        for (int kk = 0; kk < BK; kk++) {
            float a[8], b[8];
            *(float4*)&a[0] = *(const float4*)&As[kk][ty * 8];
            *(float4*)&a[4] = *(const float4*)&As[kk][ty * 8 + 4];
            *(float4*)&b[0] = *(const float4*)&Bs[kk][tx * 8];
            *(float4*)&b[4] = *(const float4*)&Bs[kk][tx * 8 + 4];
#pragma unroll
            for (int i = 0; i < 8; i++)
#pragma unroll
                for (int j = 0; j < 8; j++) acc[i][j] = fmaf(a[i], b[j], acc[i][j]);
        }
        __syncthreads();
    }

    // Epilogue (+ optional RoPE). Columns per thread are 8 consecutive,
    // starting at a multiple of 8, so rotary pairs (even,odd) are local.
    float inv_freq[4];
    if (rope) {
#pragma unroll
        for (int jp = 0; jp < 4; jp++) {
            int e = n0 + tx * 8 + jp * 2;
            int d = e & (HD - 1);                 // even head-local index
            inv_freq[jp] = powf(10000.f, -(float)d / (float)HD);
        }
    }
#pragma unroll
    for (int i = 0; i < 8; i++) {
        int m = m0 + ty * 8 + i;   // sequence position
        if (rope) {
#pragma unroll
            for (int jp = 0; jp < 4; jp++) {
                float ang = (float)m * inv_freq[jp];
                float sv, cv;
                sincosf(ang, &sv, &cv);
                float x1 = acc[i][jp * 2 + 0];
                float x2 = acc[i][jp * 2 + 1];
                acc[i][jp * 2 + 0] = x1 * cv - x2 * sv;
                acc[i][jp * 2 + 1] = x1 * sv + x2 * cv;
            }
        }
        float4* Crow = (float4*)(C + (size_t)m * DIM + n0 + tx * 8);
        Crow[0] = make_float4(acc[i][0], acc[i][1], acc[i][2], acc[i][3]);
        Crow[1] = make_float4(acc[i][4], acc[i][5], acc[i][6], acc[i][7]);
    }
}

// ---------------------------------------------------------------------------
// Sliding-window causal attention, flash-style online softmax.
// CTA = (64 queries, 1 head). Key tiles of 64 over [max(0,q0-512), q0+64).
// Each query q attends keys in [q-511, q] ∩ [0, q].
// ---------------------------------------------------------------------------
#define AQ 64
#define AK 64
#define APAD 4
#define DSTRIDE (HD + APAD)   // 68, 16B-aligned rows
#define KSTRIDE (AK + APAD)   // 68

#define ATTN_SMEM_FLOATS (AQ * DSTRIDE + HD * KSTRIDE + AK * DSTRIDE + AQ * KSTRIDE + 2 * AQ)
#define ATTN_SMEM_BYTES  (ATTN_SMEM_FLOATS * 4)

__global__ void __launch_bounds__(256) attn_kernel()
{
    extern __shared__ float sm[];
    float* Qs   = sm;                         // [AQ][DSTRIDE]   q-major
    float* Kst  = Qs + AQ * DSTRIDE;          // [HD][KSTRIDE]   d-major (transposed)
    float* Vs   = Kst + HD * KSTRIDE;         // [AK][DSTRIDE]   key-major
    float* Ss   = Vs + AK * DSTRIDE;          // [AQ][KSTRIDE]   scores -> probs
    float* alph = Ss + AQ * KSTRIDE;          // [AQ]
    float* lsum = alph + AQ;                  // [AQ]

    const int tid = threadIdx.x;
    const int tx = tid & 15;     // 16 key / dcol groups
    const int ty = tid >> 4;     // 16 row groups
    const int q0 = blockIdx.x * AQ;
    const int h  = blockIdx.y;

    // Load Q tile [64 q][64 d]
    {
        int r = tid >> 2;
        int cb = (tid & 3) << 4;
#pragma unroll
        for (int p = 0; p < 4; p++) {
            int c = cb + p * 4;
            *(float4*)&Qs[r * DSTRIDE + c] =
                *(const float4*)&g_q[(size_t)(q0 + r) * DIM + h * HD + c];
        }
    }

    float o[4][4];
#pragma unroll
    for (int i = 0; i < 4; i++)
#pragma unroll
        for (int j = 0; j < 4; j++) o[i][j] = 0.f;
    float m_i = -INFINITY, l_i = 0.f;

    const int gk_start = (q0 - WIN > 0) ? (q0 - WIN) : 0;

    for (int gk0 = gk_start; gk0 < q0 + AQ; gk0 += AK) {
        __syncthreads();   // previous tile's Vs/Ss fully consumed

        // Load K (transposed to d-major) and V (key-major)
        {
            int r = tid >> 2;          // key row 0..63
            int cb = (tid & 3) << 4;   // d base
#pragma unroll
            for (int p = 0; p < 4; p++) {
                int c = cb + p * 4;
                float4 kv = *(const float4*)&g_k[(size_t)(gk0 + r) * DIM + h * HD + c];
                Kst[(c + 0) * KSTRIDE + r] = kv.x;
                Kst[(c + 1) * KSTRIDE + r] = kv.y;
                Kst[(c + 2) * KSTRIDE + r] = kv.z;
                Kst[(c + 3) * KSTRIDE + r] = kv.w;
                *(float4*)&Vs[r * DSTRIDE + c] =
                    *(const float4*)&g_v[(size_t)(gk0 + r) * DIM + h * HD + c];
            }
        }
        __syncthreads();

        // S = Q K^T : rows ty*4+i, keys tx*4+j
        float s[4][4];
#pragma unroll
        for (int i = 0; i < 4; i++)
#pragma unroll
            for (int j = 0; j < 4; j++) s[i][j] = 0.f;
#pragma unroll
        for (int kk = 0; kk < HD; kk++) {
            float4 b4 = *(const float4*)&Kst[kk * KSTRIDE + tx * 4];
            float b[4] = {b4.x, b4.y, b4.z, b4.w};
            float a[4];
#pragma unroll
            for (int i = 0; i < 4; i++) a[i] = Qs[(ty * 4 + i) * DSTRIDE + kk];
#pragma unroll
            for (int i = 0; i < 4; i++)
#pragma unroll
                for (int j = 0; j < 4; j++) s[i][j] = fmaf(a[i], b[j], s[i][j]);
        }
#pragma unroll
        for (int i = 0; i < 4; i++)
            *(float4*)&Ss[(ty * 4 + i) * KSTRIDE + tx * 4] =
                make_float4(s[i][0], s[i][1], s[i][2], s[i][3]);
        __syncthreads();

        // Online softmax: one thread per query row (tid < 64), mask applied here.
        if (tid < AQ) {
            const int q = q0 + tid;
            int clo = q - WIN + 1 - gk0; if (clo < 0) clo = 0;
            int chi = q - gk0;           if (chi > AK - 1) chi = AK - 1;
            float mt = -INFINITY;
            for (int c = clo; c <= chi; c++)
                mt = fmaxf(mt, Ss[tid * KSTRIDE + c] * 0.125f);
            float m_new = fmaxf(m_i, mt);
            float alpha = (m_new == -INFINITY) ? 1.f : __expf(m_i - m_new);
            float ls = 0.f;
            for (int c = 0; c < AK; c++) {
                float p = 0.f;
                if (c >= clo && c <= chi)
                    p = __expf(Ss[tid * KSTRIDE + c] * 0.125f - m_new);
                Ss[tid * KSTRIDE + c] = p;
                ls += p;
            }
            l_i = l_i * alpha + ls;
            m_i = m_new;
            alph[tid] = alpha;
        }
        __syncthreads();

        // Rescale O, accumulate P @ V : rows ty*4+i, d-cols tx*4+j
        float al[4];
#pragma unroll
        for (int i = 0; i < 4; i++) al[i] = alph[ty * 4 + i];
#pragma unroll
        for (int i = 0; i < 4; i++)
#pragma unroll
            for (int j = 0; j < 4; j++) o[i][j] *= al[i];
#pragma unroll
        for (int key = 0; key < AK; key++) {
            float4 v4 = *(const float4*)&Vs[key * DSTRIDE + tx * 4];
            float vv[4] = {v4.x, v4.y, v4.z, v4.w};
            float p[4];
#pragma unroll
            for (int i = 0; i < 4; i++) p[i] = Ss[(ty * 4 + i) * KSTRIDE + key];
#pragma unroll
            for (int i = 0; i < 4; i++)
#pragma unroll
                for (int j = 0; j < 4; j++) o[i][j] = fmaf(p[i], vv[j], o[i][j]);
        }
    }

    if (tid < AQ) lsum[tid] = l_i;
    __syncthreads();

#pragma unroll
    for (int i = 0; i < 4; i++) {
        float inv_l = 1.f / lsum[ty * 4 + i];
        int q = q0 + ty * 4 + i;
        *(float4*)&g_o[(size_t)q * DIM + h * HD + tx * 4] =
            make_float4(o[i][0] * inv_l, o[i][1] * inv_l, o[i][2] * inv_l, o[i][3] * inv_l);
    }
}

// ---------------------------------------------------------------------------
extern "C" void kernel_launch(void* const* d_in, const int* in_sizes, int n_in,
                              void* d_out, int out_size)
{
    const float* x  = (const float*)d_in[0];
    const float* Wq = (const float*)d_in[1];
    const float* Wk = (const float*)d_in[2];
    const float* Wv = (const float*)d_in[3];
    const float* Wo = (const float*)d_in[4];
    float* out = (float*)d_out;

    float *pq, *pk, *pv, *po;
    cudaGetSymbolAddress((void**)&pq, g_q);
    cudaGetSymbolAddress((void**)&pk, g_k);
    cudaGetSymbolAddress((void**)&pv, g_v);
    cudaGetSymbolAddress((void**)&po, g_o);

    cudaFuncSetAttribute(attn_kernel, cudaFuncAttributeMaxDynamicSharedMemorySize,
                         ATTN_SMEM_BYTES);

    dim3 blk(256);

    // QKV projections + fused RoPE on q,k (rope_mask bits 0,1)
    dim3 g_qkv(DIM / BN, S_LEN / BM, 3);
    sgemm_nt<<<g_qkv, blk>>>(x, Wq, Wk, Wv, pq, pk, pv, 0x3);

    // Sliding-window attention
    dim3 g_att(S_LEN / AQ, NH);
    attn_kernel<<<g_att, blk, ATTN_SMEM_BYTES>>>();

    // Output projection
    dim3 g_out(DIM / BN, S_LEN / BM, 1);
    sgemm_nt<<<g_out, blk>>>(po, Wo, Wo, Wo, out, out, out, 0);
}

// round 4
// speedup vs baseline: 1.7358x; 1.7358x over previous
#include <cuda_runtime.h>
#include <cuda_bf16.h>
#include <math.h>
#include <stdint.h>

// Problem constants (dataset fixed; window_size input == 512)
#define S_LEN 8192
#define DIM   1024
#define NH    16
#define HD    64
#define WIN   512

// ---------------------------------------------------------------------------
// Device scratch (allocation-free rule: __device__ globals)
// ---------------------------------------------------------------------------
__device__ float g_q[S_LEN * DIM];
__device__ float g_k[S_LEN * DIM];
__device__ float g_v[S_LEN * DIM];
__device__ float g_o[S_LEN * DIM];

__device__ __nv_bfloat16 g_x_hi[S_LEN * DIM];
__device__ __nv_bfloat16 g_x_lo[S_LEN * DIM];
__device__ __nv_bfloat16 g_o_hi[S_LEN * DIM];
__device__ __nv_bfloat16 g_o_lo[S_LEN * DIM];
__device__ __nv_bfloat16 g_w_hi[4 * DIM * DIM];   // q,k,v,o
__device__ __nv_bfloat16 g_w_lo[4 * DIM * DIM];

// ---------------------------------------------------------------------------
// PTX helpers: sm_80-era tensor path (compiles on plain sm_100 target)
// ---------------------------------------------------------------------------
__device__ __forceinline__ uint32_t smem_u32(const void* p) {
    uint32_t a;
    asm("{ .reg .u64 t; cvta.to.shared.u64 t, %1; cvt.u32.u64 %0, t; }"
        : "=r"(a) : "l"(p));
    return a;
}

__device__ __forceinline__ void cp_async16(uint32_t dst, const void* src) {
    asm volatile("cp.async.cg.shared.global [%0], [%1], 16;"
                 :: "r"(dst), "l"(src) : "memory");
}
__device__ __forceinline__ void cp_commit() {
    asm volatile("cp.async.commit_group;" ::: "memory");
}
__device__ __forceinline__ void cp_wait0() {
    asm volatile("cp.async.wait_group 0;" ::: "memory");
}

__device__ __forceinline__ void ldmx4(uint32_t* r, uint32_t addr) {
    asm volatile("ldmatrix.sync.aligned.m8n8.x4.shared.b16 {%0,%1,%2,%3}, [%4];"
                 : "=r"(r[0]), "=r"(r[1]), "=r"(r[2]), "=r"(r[3]) : "r"(addr));
}

__device__ __forceinline__ void mma16816(float* d, const uint32_t* a, const uint32_t* b) {
    asm volatile(
        "mma.sync.aligned.m16n8k16.row.col.f32.bf16.bf16.f32 "
        "{%0,%1,%2,%3}, {%4,%5,%6,%7}, {%8,%9}, {%0,%1,%2,%3};"
        : "+f"(d[0]), "+f"(d[1]), "+f"(d[2]), "+f"(d[3])
        : "r"(a[0]), "r"(a[1]), "r"(a[2]), "r"(a[3]), "r"(b[0]), "r"(b[1]));
}

// ---------------------------------------------------------------------------
// fp32 -> bf16 hi/lo split
// ---------------------------------------------------------------------------
__global__ void split_kernel(const float* __restrict__ src,
                             __nv_bfloat16* __restrict__ hi,
                             __nv_bfloat16* __restrict__ lo, int n4) {
    int i = blockIdx.x * blockDim.x + threadIdx.x;
    if (i >= n4) return;
    float4 v = ((const float4*)src)[i];
    __nv_bfloat16 h[4], l[4];
    float vv[4] = {v.x, v.y, v.z, v.w};
#pragma unroll
    for (int j = 0; j < 4; j++) {
        h[j] = __float2bfloat16(vv[j]);
        l[j] = __float2bfloat16(vv[j] - __bfloat162float(h[j]));
    }
    ((uint2*)hi)[i] = *(uint2*)h;
    ((uint2*)lo)[i] = *(uint2*)l;
}

// ---------------------------------------------------------------------------
// Split-bf16 GEMM via mma.sync (NT): C[m,n] = sum_k A[m,k] * W[n,k]
// CTA tile 128x128, BK=32, 8 warps (4 m-blocks x 2 n-blocks of 32x64).
// cp.async double buffering; 3 mma combos (hh, hl, lh); fused RoPE epilogue.
// ---------------------------------------------------------------------------
#define GBM 128
#define GBN 128
#define GBK 32
#define NCHUNK (DIM / GBK)        // 32
#define LDS 40                    // bf16 elements per smem row (32 + 8 pad)
#define TILE_B (128 * LDS * 2)    // 10240 bytes
#define STAGE_B (4 * TILE_B)      // Ah, Al, Bh, Bl = 40960
#define GEMM_SMEM (2 * STAGE_B)   // 81920

__global__ void __launch_bounds__(256, 1) gemm_tc(
    const __nv_bfloat16* __restrict__ A_hi, const __nv_bfloat16* __restrict__ A_lo,
    const __nv_bfloat16* __restrict__ W_hi, const __nv_bfloat16* __restrict__ W_lo,
    float* __restrict__ C0, float* __restrict__ C1, float* __restrict__ C2,
    int rope_mask)
{
    extern __shared__ char smem[];
    const int tid  = threadIdx.x;
    const int lane = tid & 31;
    const int wid  = tid >> 5;
    const int wm   = wid & 3;      // m block (32 rows)
    const int wn   = wid >> 2;     // n block (64 cols)
    const int z = blockIdx.z;
    const int m0 = blockIdx.y * GBM;
    const int n0 = blockIdx.x * GBN;
    float* C = (z == 0) ? C0 : (z == 1) ? C1 : C2;
    const bool rope = (rope_mask >> z) & 1;
    const __nv_bfloat16* Bh = W_hi + (size_t)z * DIM * DIM;
    const __nv_bfloat16* Bl = W_lo + (size_t)z * DIM * DIM;

    const uint32_t sbase = smem_u32(smem);
    const __nv_bfloat16* srcs[4] = {A_hi, A_lo, Bh, Bl};
    const int row0[4] = {m0, m0, n0, n0};

    // ---- async load of chunk k0 into stage st ------------------------------
    auto prefetch = [&](int st, int k0) {
        uint32_t stage = sbase + st * STAGE_B;
#pragma unroll
        for (int it = 0; it < 8; it++) {
            int u = tid + it * 256;         // 0..2047
            int t = u >> 9;                 // tile 0..3
            int w = u & 511;
            int row = w >> 2;               // 0..127
            int ch  = w & 3;                // 16B chunk 0..3
            const __nv_bfloat16* src = srcs[t];
            cp_async16(stage + t * TILE_B + row * (LDS * 2) + ch * 16,
                       src + (size_t)(row0[t] + row) * DIM + k0 + ch * 8);
        }
        cp_commit();
    };

    float acc[2][8][4];
#pragma unroll
    for (int mt = 0; mt < 2; mt++)
#pragma unroll
        for (int nt = 0; nt < 8; nt++)
#pragma unroll
            for (int r = 0; r < 4; r++) acc[mt][nt][r] = 0.f;

    prefetch(0, 0);

    for (int c = 0; c < NCHUNK; c++) {
        cp_wait0();
        __syncthreads();
        if (c + 1 < NCHUNK) prefetch((c + 1) & 1, (c + 1) * GBK);

        uint32_t stage = sbase + (c & 1) * STAGE_B;
        uint32_t sAh = stage + 0 * TILE_B;
        uint32_t sAl = stage + 1 * TILE_B;
        uint32_t sBh = stage + 2 * TILE_B;
        uint32_t sBl = stage + 3 * TILE_B;

#pragma unroll
        for (int ks = 0; ks < 2; ks++) {  // two k16 steps per 32-chunk
            // A fragments (2 m16 tiles, hi & lo)
            uint32_t ah[2][4], al[2][4];
#pragma unroll
            for (int mt = 0; mt < 2; mt++) {
                uint32_t roff = (wm * 32 + mt * 16 + (lane & 15)) * (LDS * 2)
                              + (ks * 16 + (lane >> 4) * 8) * 2;
                ldmx4(ah[mt], sAh + roff);
                ldmx4(al[mt], sAl + roff);
            }
            // B fragments (8 n8 tiles, 2 per x4, hi & lo)
            uint32_t bh[8][2], bl[8][2];
#pragma unroll
            for (int p = 0; p < 4; p++) {
                int nloc = wn * 64 + p * 16 + (lane & 7) + ((lane >> 4) << 3);
                uint32_t roff = nloc * (LDS * 2)
                              + (ks * 16 + ((lane >> 3) & 1) * 8) * 2;
                uint32_t r4[4];
                ldmx4(r4, sBh + roff);
                bh[2 * p][0] = r4[0]; bh[2 * p][1] = r4[1];
                bh[2 * p + 1][0] = r4[2]; bh[2 * p + 1][1] = r4[3];
                ldmx4(r4, sBl + roff);
                bl[2 * p][0] = r4[0]; bl[2 * p][1] = r4[1];
                bl[2 * p + 1][0] = r4[2]; bl[2 * p + 1][1] = r4[3];
            }
#pragma unroll
            for (int mt = 0; mt < 2; mt++)
#pragma unroll
                for (int nt = 0; nt < 8; nt++) {
                    mma16816(acc[mt][nt], ah[mt], bh[nt]);  // hi*hi
                    mma16816(acc[mt][nt], ah[mt], bl[nt]);  // hi*lo
                    mma16816(acc[mt][nt], al[mt], bh[nt]);  // lo*hi
                }
        }
        __syncthreads();
    }

    // ---- epilogue: optional RoPE (pairs are register-local), store fp32 ----
#pragma unroll
    for (int mt = 0; mt < 2; mt++) {
#pragma unroll
        for (int nt = 0; nt < 8; nt++) {
            int col = n0 + wn * 64 + nt * 8 + 2 * (lane & 3);   // even
            int r_lo = m0 + wm * 32 + mt * 16 + (lane >> 2);
            int r_hi = r_lo + 8;
            float* a4 = acc[mt][nt];
            if (rope) {
                int d = col & (HD - 1);
                float inv = powf(10000.f, -(float)d / (float)HD);
                float sv, cv;
                sincosf((float)r_lo * inv, &sv, &cv);
                float x1 = a4[0], x2 = a4[1];
                a4[0] = x1 * cv - x2 * sv;
                a4[1] = x1 * sv + x2 * cv;
                sincosf((float)r_hi * inv, &sv, &cv);
                x1 = a4[2]; x2 = a4[3];
                a4[2] = x1 * cv - x2 * sv;
                a4[3] = x1 * sv + x2 * cv;
            }
            *(float2*)(C + (size_t)r_lo * DIM + col) = make_float2(a4[0], a4[1]);
            *(float2*)(C + (size_t)r_hi * DIM + col) = make_float2(a4[2], a4[3]);
        }
    }
}

// ---------------------------------------------------------------------------
// Sliding-window causal attention (fp32, flash-style online softmax) — as R1.
// ---------------------------------------------------------------------------
#define AQ 64
#define AK 64
#define APAD 4
#define DSTRIDE (HD + APAD)
#define KSTRIDE (AK + APAD)
#define ATTN_SMEM_FLOATS (AQ * DSTRIDE + HD * KSTRIDE + AK * DSTRIDE + AQ * KSTRIDE + 2 * AQ)
#define ATTN_SMEM_BYTES  (ATTN_SMEM_FLOATS * 4)

__global__ void __launch_bounds__(256) attn_kernel()
{
    extern __shared__ float sm[];
    float* Qs   = sm;
    float* Kst  = Qs + AQ * DSTRIDE;
    float* Vs   = Kst + HD * KSTRIDE;
    float* Ss   = Vs + AK * DSTRIDE;
    float* alph = Ss + AQ * KSTRIDE;
    float* lsum = alph + AQ;

    const int tid = threadIdx.x;
    const int tx = tid & 15;
    const int ty = tid >> 4;
    const int q0 = blockIdx.x * AQ;
    const int h  = blockIdx.y;

    {
        int r = tid >> 2;
        int cb = (tid & 3) << 4;
#pragma unroll
        for (int p = 0; p < 4; p++) {
            int c = cb + p * 4;
            *(float4*)&Qs[r * DSTRIDE + c] =
                *(const float4*)&g_q[(size_t)(q0 + r) * DIM + h * HD + c];
        }
    }

    float o[4][4];
#pragma unroll
    for (int i = 0; i < 4; i++)
#pragma unroll
        for (int j = 0; j < 4; j++) o[i][j] = 0.f;
    float m_i = -INFINITY, l_i = 0.f;

    const int gk_start = (q0 - WIN > 0) ? (q0 - WIN) : 0;

    for (int gk0 = gk_start; gk0 < q0 + AQ; gk0 += AK) {
        __syncthreads();
        {
            int r = tid >> 2;
            int cb = (tid & 3) << 4;
#pragma unroll
            for (int p = 0; p < 4; p++) {
                int c = cb + p * 4;
                float4 kv = *(const float4*)&g_k[(size_t)(gk0 + r) * DIM + h * HD + c];
                Kst[(c + 0) * KSTRIDE + r] = kv.x;
                Kst[(c + 1) * KSTRIDE + r] = kv.y;
                Kst[(c + 2) * KSTRIDE + r] = kv.z;
                Kst[(c + 3) * KSTRIDE + r] = kv.w;
                *(float4*)&Vs[r * DSTRIDE + c] =
                    *(const float4*)&g_v[(size_t)(gk0 + r) * DIM + h * HD + c];
            }
        }
        __syncthreads();

        float s[4][4];
#pragma unroll
        for (int i = 0; i < 4; i++)
#pragma unroll
            for (int j = 0; j < 4; j++) s[i][j] = 0.f;
#pragma unroll
        for (int kk = 0; kk < HD; kk++) {
            float4 b4 = *(const float4*)&Kst[kk * KSTRIDE + tx * 4];
            float b[4] = {b4.x, b4.y, b4.z, b4.w};
            float a[4];
#pragma unroll
            for (int i = 0; i < 4; i++) a[i] = Qs[(ty * 4 + i) * DSTRIDE + kk];
#pragma unroll
            for (int i = 0; i < 4; i++)
#pragma unroll
                for (int j = 0; j < 4; j++) s[i][j] = fmaf(a[i], b[j], s[i][j]);
        }
#pragma unroll
        for (int i = 0; i < 4; i++)
            *(float4*)&Ss[(ty * 4 + i) * KSTRIDE + tx * 4] =
                make_float4(s[i][0], s[i][1], s[i][2], s[i][3]);
        __syncthreads();

        if (tid < AQ) {
            const int q = q0 + tid;
            int clo = q - WIN + 1 - gk0; if (clo < 0) clo = 0;
            int chi = q - gk0;           if (chi > AK - 1) chi = AK - 1;
            float mt = -INFINITY;
            for (int c = clo; c <= chi; c++)
                mt = fmaxf(mt, Ss[tid * KSTRIDE + c] * 0.125f);
            float m_new = fmaxf(m_i, mt);
            float alpha = (m_new == -INFINITY) ? 1.f : __expf(m_i - m_new);
            float ls = 0.f;
            for (int c = 0; c < AK; c++) {
                float p = 0.f;
                if (c >= clo && c <= chi)
                    p = __expf(Ss[tid * KSTRIDE + c] * 0.125f - m_new);
                Ss[tid * KSTRIDE + c] = p;
                ls += p;
            }
            l_i = l_i * alpha + ls;
            m_i = m_new;
            alph[tid] = alpha;
        }
        __syncthreads();

        float al[4];
#pragma unroll
        for (int i = 0; i < 4; i++) al[i] = alph[ty * 4 + i];
#pragma unroll
        for (int i = 0; i < 4; i++)
#pragma unroll
            for (int j = 0; j < 4; j++) o[i][j] *= al[i];
#pragma unroll
        for (int key = 0; key < AK; key++) {
            float4 v4 = *(const float4*)&Vs[key * DSTRIDE + tx * 4];
            float vv[4] = {v4.x, v4.y, v4.z, v4.w};
            float p[4];
#pragma unroll
            for (int i = 0; i < 4; i++) p[i] = Ss[(ty * 4 + i) * KSTRIDE + key];
#pragma unroll
            for (int i = 0; i < 4; i++)
#pragma unroll
                for (int j = 0; j < 4; j++) o[i][j] = fmaf(p[i], vv[j], o[i][j]);
        }
    }

    if (tid < AQ) lsum[tid] = l_i;
    __syncthreads();

#pragma unroll
    for (int i = 0; i < 4; i++) {
        float inv_l = 1.f / lsum[ty * 4 + i];
        int q = q0 + ty * 4 + i;
        *(float4*)&g_o[(size_t)q * DIM + h * HD + tx * 4] =
            make_float4(o[i][0] * inv_l, o[i][1] * inv_l, o[i][2] * inv_l, o[i][3] * inv_l);
    }
}

// ---------------------------------------------------------------------------
extern "C" void kernel_launch(void* const* d_in, const int* in_sizes, int n_in,
                              void* d_out, int out_size)
{
    const float* x  = (const float*)d_in[0];
    const float* Wq = (const float*)d_in[1];
    const float* Wk = (const float*)d_in[2];
    const float* Wv = (const float*)d_in[3];
    const float* Wo = (const float*)d_in[4];
    float* out = (float*)d_out;

    float *pq, *pk, *pv, *po;
    cudaGetSymbolAddress((void**)&pq, g_q);
    cudaGetSymbolAddress((void**)&pk, g_k);
    cudaGetSymbolAddress((void**)&pv, g_v);
    cudaGetSymbolAddress((void**)&po, g_o);
    __nv_bfloat16 *xh, *xl, *oh, *ol, *wh, *wl;
    cudaGetSymbolAddress((void**)&xh, g_x_hi);
    cudaGetSymbolAddress((void**)&xl, g_x_lo);
    cudaGetSymbolAddress((void**)&oh, g_o_hi);
    cudaGetSymbolAddress((void**)&ol, g_o_lo);
    cudaGetSymbolAddress((void**)&wh, g_w_hi);
    cudaGetSymbolAddress((void**)&wl, g_w_lo);

    cudaFuncSetAttribute(attn_kernel, cudaFuncAttributeMaxDynamicSharedMemorySize,
                         ATTN_SMEM_BYTES);
    cudaFuncSetAttribute(gemm_tc, cudaFuncAttributeMaxDynamicSharedMemorySize,
                         GEMM_SMEM);

    const int WELEM = DIM * DIM;

    // 1) splits: x and the 4 weight matrices
    split_kernel<<<(S_LEN * DIM / 4 + 255) / 256, 256>>>(x, xh, xl, S_LEN * DIM / 4);
    split_kernel<<<(WELEM / 4 + 255) / 256, 256>>>(Wq, wh + 0 * WELEM, wl + 0 * WELEM, WELEM / 4);
    split_kernel<<<(WELEM / 4 + 255) / 256, 256>>>(Wk, wh + 1 * WELEM, wl + 1 * WELEM, WELEM / 4);
    split_kernel<<<(WELEM / 4 + 255) / 256, 256>>>(Wv, wh + 2 * WELEM, wl + 2 * WELEM, WELEM / 4);
    split_kernel<<<(WELEM / 4 + 255) / 256, 256>>>(Wo, wh + 3 * WELEM, wl + 3 * WELEM, WELEM / 4);

    // 2) QKV projections + fused RoPE on q,k
    dim3 g_qkv(DIM / GBN, S_LEN / GBM, 3);
    gemm_tc<<<g_qkv, 256, GEMM_SMEM>>>(xh, xl, wh, wl, pq, pk, pv, 0x3);

    // 3) sliding-window attention
    dim3 g_att(S_LEN / AQ, NH);
    attn_kernel<<<g_att, 256, ATTN_SMEM_BYTES>>>();

    // 4) split attention output, output projection
    split_kernel<<<(S_LEN * DIM / 4 + 255) / 256, 256>>>(po, oh, ol, S_LEN * DIM / 4);
    dim3 g_out(DIM / GBN, S_LEN / GBM, 1);
    gemm_tc<<<g_out, 256, GEMM_SMEM>>>(oh, ol, wh + 3 * WELEM, wl + 3 * WELEM,
                                       out, out, out, 0);
}

// round 5
// speedup vs baseline: 2.0779x; 1.1971x over previous
#include <cuda_runtime.h>
#include <cuda_bf16.h>
#include <math.h>
#include <stdint.h>

// Problem constants (dataset fixed; window_size input == 512)
#define S_LEN 8192
#define DIM   1024
#define NH    16
#define HD    64
#define WIN   512

// ---------------------------------------------------------------------------
// Device scratch (allocation-free rule: __device__ globals)
// ---------------------------------------------------------------------------
__device__ float g_q[S_LEN * DIM];
__device__ float g_k[S_LEN * DIM];
__device__ float g_v[S_LEN * DIM];

__device__ __nv_bfloat16 g_x_hi[S_LEN * DIM];
__device__ __nv_bfloat16 g_x_lo[S_LEN * DIM];
__device__ __nv_bfloat16 g_o_hi[S_LEN * DIM];
__device__ __nv_bfloat16 g_o_lo[S_LEN * DIM];
__device__ __nv_bfloat16 g_w_hi[4 * DIM * DIM];   // q,k,v,o
__device__ __nv_bfloat16 g_w_lo[4 * DIM * DIM];

// ---------------------------------------------------------------------------
// PTX helpers (sm_80-era tensor path; compiles on plain sm_100 target)
// ---------------------------------------------------------------------------
__device__ __forceinline__ uint32_t smem_u32(const void* p) {
    uint32_t a;
    asm("{ .reg .u64 t; cvta.to.shared.u64 t, %1; cvt.u32.u64 %0, t; }"
        : "=r"(a) : "l"(p));
    return a;
}
__device__ __forceinline__ void cp_async16(uint32_t dst, const void* src) {
    asm volatile("cp.async.cg.shared.global [%0], [%1], 16;"
                 :: "r"(dst), "l"(src) : "memory");
}
__device__ __forceinline__ void cp_commit() {
    asm volatile("cp.async.commit_group;" ::: "memory");
}
__device__ __forceinline__ void cp_wait0() {
    asm volatile("cp.async.wait_group 0;" ::: "memory");
}
__device__ __forceinline__ void ldmx4(uint32_t* r, uint32_t addr) {
    asm volatile("ldmatrix.sync.aligned.m8n8.x4.shared.b16 {%0,%1,%2,%3}, [%4];"
                 : "=r"(r[0]), "=r"(r[1]), "=r"(r[2]), "=r"(r[3]) : "r"(addr));
}
__device__ __forceinline__ void mma16816(float* d, const uint32_t* a, const uint32_t* b) {
    asm volatile(
        "mma.sync.aligned.m16n8k16.row.col.f32.bf16.bf16.f32 "
        "{%0,%1,%2,%3}, {%4,%5,%6,%7}, {%8,%9}, {%0,%1,%2,%3};"
        : "+f"(d[0]), "+f"(d[1]), "+f"(d[2]), "+f"(d[3])
        : "r"(a[0]), "r"(a[1]), "r"(a[2]), "r"(a[3]), "r"(b[0]), "r"(b[1]));
}

// ---------------------------------------------------------------------------
// fp32 -> bf16 hi/lo splits
// ---------------------------------------------------------------------------
__device__ __forceinline__ void split4(const float* vv, uint2& h2, uint2& l2) {
    __nv_bfloat16 h[4], l[4];
#pragma unroll
    for (int j = 0; j < 4; j++) {
        h[j] = __float2bfloat16(vv[j]);
        l[j] = __float2bfloat16(vv[j] - __bfloat162float(h[j]));
    }
    h2 = *(uint2*)h;
    l2 = *(uint2*)l;
}

__global__ void split_kernel(const float* __restrict__ src,
                             __nv_bfloat16* __restrict__ hi,
                             __nv_bfloat16* __restrict__ lo, int n4) {
    int i = blockIdx.x * blockDim.x + threadIdx.x;
    if (i >= n4) return;
    float4 v = ((const float4*)src)[i];
    float vv[4] = {v.x, v.y, v.z, v.w};
    uint2 h2, l2;
    split4(vv, h2, l2);
    ((uint2*)hi)[i] = h2;
    ((uint2*)lo)[i] = l2;
}

__global__ void split2_kernel(const float* __restrict__ s0, const float* __restrict__ s1,
                              __nv_bfloat16* __restrict__ h0, __nv_bfloat16* __restrict__ l0,
                              __nv_bfloat16* __restrict__ h1, __nv_bfloat16* __restrict__ l1,
                              int n4) {
    const float* s = blockIdx.y ? s1 : s0;
    __nv_bfloat16* hh = blockIdx.y ? h1 : h0;
    __nv_bfloat16* ll = blockIdx.y ? l1 : l0;
    int i = blockIdx.x * blockDim.x + threadIdx.x;
    if (i >= n4) return;
    float4 v = ((const float4*)s)[i];
    float vv[4] = {v.x, v.y, v.z, v.w};
    uint2 h2, l2;
    split4(vv, h2, l2);
    ((uint2*)hh)[i] = h2;
    ((uint2*)ll)[i] = l2;
}

// ---------------------------------------------------------------------------
// Split-bf16 GEMM via mma.sync (NT): C[m,n] = sum_k A[m,k] * W[n,k]
// CTA tile 128x128, BK=32, 8 warps (4 m-blocks x 2 n-blocks of 32x64).
// cp.async double buffering; 3 mma combos (hh, hl, lh); fused RoPE epilogue.
// ---------------------------------------------------------------------------
#define GBM 128
#define GBN 128
#define GBK 32
#define NCHUNK (DIM / GBK)        // 32
#define LDS 40                    // bf16 per smem row (32 + 8 pad)
#define TILE_B (128 * LDS * 2)    // 10240 bytes
#define STAGE_B (4 * TILE_B)      // Ah, Al, Bh, Bl = 40960
#define GEMM_SMEM (2 * STAGE_B)   // 81920

__global__ void __launch_bounds__(256, 2) gemm_tc(
    const __nv_bfloat16* __restrict__ A_hi, const __nv_bfloat16* __restrict__ A_lo,
    const __nv_bfloat16* __restrict__ W_hi, const __nv_bfloat16* __restrict__ W_lo,
    float* __restrict__ C0, float* __restrict__ C1, float* __restrict__ C2,
    int rope_mask)
{
    extern __shared__ char smem[];
    const int tid  = threadIdx.x;
    const int lane = tid & 31;
    const int wid  = tid >> 5;
    const int wm   = wid & 3;      // m block (32 rows)
    const int wn   = wid >> 2;     // n block (64 cols)
    const int z = blockIdx.z;
    const int m0 = blockIdx.y * GBM;
    const int n0 = blockIdx.x * GBN;
    float* C = (z == 0) ? C0 : (z == 1) ? C1 : C2;
    const bool rope = (rope_mask >> z) & 1;
    const __nv_bfloat16* Bh = W_hi + (size_t)z * DIM * DIM;
    const __nv_bfloat16* Bl = W_lo + (size_t)z * DIM * DIM;

    const uint32_t sbase = smem_u32(smem);

    // Compile-time tile selection: no runtime-indexed pointer array (no LDL).
    auto prefetch = [&](int st, int k0) {
        uint32_t stage = sbase + st * STAGE_B;
#pragma unroll
        for (int half = 0; half < 2; half++) {
            int u = tid + half * 256;          // 0..511
            int row = u >> 2;                  // 0..127
            int ch  = u & 3;                   // 16B chunk
            uint32_t doff = row * (LDS * 2) + ch * 16;
            size_t aoff = (size_t)(m0 + row) * DIM + k0 + ch * 8;
            size_t boff = (size_t)(n0 + row) * DIM + k0 + ch * 8;
            cp_async16(stage + 0 * TILE_B + doff, A_hi + aoff);
            cp_async16(stage + 1 * TILE_B + doff, A_lo + aoff);
            cp_async16(stage + 2 * TILE_B + doff, Bh + boff);
            cp_async16(stage + 3 * TILE_B + doff, Bl + boff);
        }
        cp_commit();
    };

    float acc[2][8][4];
#pragma unroll
    for (int mt = 0; mt < 2; mt++)
#pragma unroll
        for (int nt = 0; nt < 8; nt++)
#pragma unroll
            for (int r = 0; r < 4; r++) acc[mt][nt][r] = 0.f;

    prefetch(0, 0);

    for (int c = 0; c < NCHUNK; c++) {
        cp_wait0();
        __syncthreads();
        if (c + 1 < NCHUNK) prefetch((c + 1) & 1, (c + 1) * GBK);

        uint32_t stage = sbase + (c & 1) * STAGE_B;
        uint32_t sAh = stage + 0 * TILE_B;
        uint32_t sAl = stage + 1 * TILE_B;
        uint32_t sBh = stage + 2 * TILE_B;
        uint32_t sBl = stage + 3 * TILE_B;

#pragma unroll
        for (int ks = 0; ks < 2; ks++) {
            uint32_t ah[2][4], al[2][4];
#pragma unroll
            for (int mt = 0; mt < 2; mt++) {
                uint32_t roff = (wm * 32 + mt * 16 + (lane & 15)) * (LDS * 2)
                              + (ks * 16 + (lane >> 4) * 8) * 2;
                ldmx4(ah[mt], sAh + roff);
                ldmx4(al[mt], sAl + roff);
            }
#pragma unroll
            for (int p = 0; p < 4; p++) {
                int nloc = wn * 64 + p * 16 + (lane & 7) + ((lane >> 4) << 3);
                uint32_t roff = nloc * (LDS * 2)
                              + (ks * 16 + ((lane >> 3) & 1) * 8) * 2;
                uint32_t bh[2][2], bl[2][2], r4[4];
                ldmx4(r4, sBh + roff);
                bh[0][0] = r4[0]; bh[0][1] = r4[1];
                bh[1][0] = r4[2]; bh[1][1] = r4[3];
                ldmx4(r4, sBl + roff);
                bl[0][0] = r4[0]; bl[0][1] = r4[1];
                bl[1][0] = r4[2]; bl[1][1] = r4[3];
#pragma unroll
                for (int mt = 0; mt < 2; mt++)
#pragma unroll
                    for (int e = 0; e < 2; e++) {
                        float* a4 = acc[mt][2 * p + e];
                        mma16816(a4, ah[mt], bh[e]);  // hi*hi
                        mma16816(a4, ah[mt], bl[e]);  // hi*lo
                        mma16816(a4, al[mt], bh[e]);  // lo*hi
                    }
            }
        }
        // no trailing barrier: double buffer + top-of-loop barrier suffice
    }

    // ---- epilogue: optional RoPE (pairs register-local), store fp32 --------
#pragma unroll
    for (int mt = 0; mt < 2; mt++) {
#pragma unroll
        for (int nt = 0; nt < 8; nt++) {
            int col = n0 + wn * 64 + nt * 8 + 2 * (lane & 3);   // even
            int r_lo = m0 + wm * 32 + mt * 16 + (lane >> 2);
            int r_hi = r_lo + 8;
            float* a4 = acc[mt][nt];
            if (rope) {
                int d = col & (HD - 1);
                float inv = powf(10000.f, -(float)d / (float)HD);
                float sv, cv;
                sincosf((float)r_lo * inv, &sv, &cv);
                float x1 = a4[0], x2 = a4[1];
                a4[0] = x1 * cv - x2 * sv;
                a4[1] = x1 * sv + x2 * cv;
                sincosf((float)r_hi * inv, &sv, &cv);
                x1 = a4[2]; x2 = a4[3];
                a4[2] = x1 * cv - x2 * sv;
                a4[3] = x1 * sv + x2 * cv;
            }
            *(float2*)(C + (size_t)r_lo * DIM + col) = make_float2(a4[0], a4[1]);
            *(float2*)(C + (size_t)r_hi * DIM + col) = make_float2(a4[2], a4[3]);
        }
    }
}

// ---------------------------------------------------------------------------
// Sliding-window causal attention, fp32 flash-style online softmax.
// Softmax parallelized 4 threads/row (quad shfl reductions).
// Epilogue writes bf16 hi/lo of O directly (feeds the output projection).
// ---------------------------------------------------------------------------
#define AQ 64
#define AK 64
#define APAD 4
#define DSTRIDE (HD + APAD)
#define KSTRIDE (AK + APAD)
#define ATTN_SMEM_FLOATS (AQ * DSTRIDE + HD * KSTRIDE + AK * DSTRIDE + AQ * KSTRIDE + 2 * AQ)
#define ATTN_SMEM_BYTES  (ATTN_SMEM_FLOATS * 4)

__global__ void __launch_bounds__(256) attn_kernel()
{
    extern __shared__ float sm[];
    float* Qs   = sm;
    float* Kst  = Qs + AQ * DSTRIDE;
    float* Vs   = Kst + HD * KSTRIDE;
    float* Ss   = Vs + AK * DSTRIDE;
    float* alph = Ss + AQ * KSTRIDE;
    float* lsum = alph + AQ;

    const int tid = threadIdx.x;
    const int tx = tid & 15;
    const int ty = tid >> 4;
    const int row = tid >> 2;     // softmax: 4 threads per query row
    const int sub = tid & 3;      // 16-column segment
    const int q0 = blockIdx.x * AQ;
    const int h  = blockIdx.y;

    {
        int r = tid >> 2;
        int cb = (tid & 3) << 4;
#pragma unroll
        for (int p = 0; p < 4; p++) {
            int c = cb + p * 4;
            *(float4*)&Qs[r * DSTRIDE + c] =
                *(const float4*)&g_q[(size_t)(q0 + r) * DIM + h * HD + c];
        }
    }

    float o[4][4];
#pragma unroll
    for (int i = 0; i < 4; i++)
#pragma unroll
        for (int j = 0; j < 4; j++) o[i][j] = 0.f;
    float m_i = -INFINITY, l_i = 0.f;

    const int gk_start = (q0 - WIN > 0) ? (q0 - WIN) : 0;

    for (int gk0 = gk_start; gk0 < q0 + AQ; gk0 += AK) {
        __syncthreads();
        {
            int r = tid >> 2;
            int cb = (tid & 3) << 4;
#pragma unroll
            for (int p = 0; p < 4; p++) {
                int c = cb + p * 4;
                float4 kv = *(const float4*)&g_k[(size_t)(gk0 + r) * DIM + h * HD + c];
                Kst[(c + 0) * KSTRIDE + r] = kv.x;
                Kst[(c + 1) * KSTRIDE + r] = kv.y;
                Kst[(c + 2) * KSTRIDE + r] = kv.z;
                Kst[(c + 3) * KSTRIDE + r] = kv.w;
                *(float4*)&Vs[r * DSTRIDE + c] =
                    *(const float4*)&g_v[(size_t)(gk0 + r) * DIM + h * HD + c];
            }
        }
        __syncthreads();

        // S = Q K^T
        float s[4][4];
#pragma unroll
        for (int i = 0; i < 4; i++)
#pragma unroll
            for (int j = 0; j < 4; j++) s[i][j] = 0.f;
#pragma unroll
        for (int kk = 0; kk < HD; kk++) {
            float4 b4 = *(const float4*)&Kst[kk * KSTRIDE + tx * 4];
            float b[4] = {b4.x, b4.y, b4.z, b4.w};
            float a[4];
#pragma unroll
            for (int i = 0; i < 4; i++) a[i] = Qs[(ty * 4 + i) * DSTRIDE + kk];
#pragma unroll
            for (int i = 0; i < 4; i++)
#pragma unroll
                for (int j = 0; j < 4; j++) s[i][j] = fmaf(a[i], b[j], s[i][j]);
        }
#pragma unroll
        for (int i = 0; i < 4; i++)
            *(float4*)&Ss[(ty * 4 + i) * KSTRIDE + tx * 4] =
                make_float4(s[i][0], s[i][1], s[i][2], s[i][3]);
        __syncthreads();

        // Online softmax: 4 threads/row, 16 cols each, quad shfl reductions.
        {
            const int q = q0 + row;
            int clo = q - WIN + 1 - gk0; if (clo < 0) clo = 0;
            int chi = q - gk0;           if (chi > AK - 1) chi = AK - 1;
            float sv[16];
            float mt = -INFINITY;
#pragma unroll
            for (int v4i = 0; v4i < 4; v4i++) {
                float4 s4 = *(const float4*)&Ss[row * KSTRIDE + sub * 16 + v4i * 4];
                float t4[4] = {s4.x, s4.y, s4.z, s4.w};
#pragma unroll
                for (int jj = 0; jj < 4; jj++) {
                    int c = sub * 16 + v4i * 4 + jj;
                    bool ok = (c >= clo) & (c <= chi);
                    sv[v4i * 4 + jj] = ok ? t4[jj] * 0.125f : -INFINITY;
                    mt = fmaxf(mt, sv[v4i * 4 + jj]);
                }
            }
            mt = fmaxf(mt, __shfl_xor_sync(0xffffffffu, mt, 1));
            mt = fmaxf(mt, __shfl_xor_sync(0xffffffffu, mt, 2));
            float m_new = fmaxf(m_i, mt);
            float alpha = (m_new == -INFINITY) ? 1.f : __expf(m_i - m_new);
            float ls = 0.f;
#pragma unroll
            for (int v4i = 0; v4i < 4; v4i++) {
                float p4[4];
#pragma unroll
                for (int jj = 0; jj < 4; jj++) {
                    float pv = (sv[v4i * 4 + jj] == -INFINITY)
                                   ? 0.f : __expf(sv[v4i * 4 + jj] - m_new);
                    p4[jj] = pv;
                    ls += pv;
                }
                *(float4*)&Ss[row * KSTRIDE + sub * 16 + v4i * 4] =
                    make_float4(p4[0], p4[1], p4[2], p4[3]);
            }
            ls += __shfl_xor_sync(0xffffffffu, ls, 1);
            ls += __shfl_xor_sync(0xffffffffu, ls, 2);
            l_i = l_i * alpha + ls;
            m_i = m_new;
            if (sub == 0) alph[row] = alpha;
        }
        __syncthreads();

        // Rescale O, accumulate P @ V
        float al[4];
#pragma unroll
        for (int i = 0; i < 4; i++) al[i] = alph[ty * 4 + i];
#pragma unroll
        for (int i = 0; i < 4; i++)
#pragma unroll
            for (int j = 0; j < 4; j++) o[i][j] *= al[i];
#pragma unroll
        for (int key = 0; key < AK; key++) {
            float4 v4 = *(const float4*)&Vs[key * DSTRIDE + tx * 4];
            float vv[4] = {v4.x, v4.y, v4.z, v4.w};
            float p[4];
#pragma unroll
            for (int i = 0; i < 4; i++) p[i] = Ss[(ty * 4 + i) * KSTRIDE + key];
#pragma unroll
            for (int i = 0; i < 4; i++)
#pragma unroll
                for (int j = 0; j < 4; j++) o[i][j] = fmaf(p[i], vv[j], o[i][j]);
        }
    }

    if (sub == 0) lsum[row] = l_i;
    __syncthreads();

    // Epilogue: normalize + write bf16 hi/lo directly
#pragma unroll
    for (int i = 0; i < 4; i++) {
        float inv_l = 1.f / lsum[ty * 4 + i];
        int q = q0 + ty * 4 + i;
        float vv[4] = {o[i][0] * inv_l, o[i][1] * inv_l,
                       o[i][2] * inv_l, o[i][3] * inv_l};
        uint2 h2, l2;
        split4(vv, h2, l2);
        size_t off = (size_t)q * DIM + h * HD + tx * 4;
        *(uint2*)&g_o_hi[off] = h2;
        *(uint2*)&g_o_lo[off] = l2;
    }
}

// ---------------------------------------------------------------------------
extern "C" void kernel_launch(void* const* d_in, const int* in_sizes, int n_in,
                              void* d_out, int out_size)
{
    const float* x  = (const float*)d_in[0];
    const float* Wq = (const float*)d_in[1];
    const float* Wk = (const float*)d_in[2];
    const float* Wv = (const float*)d_in[3];
    const float* Wo = (const float*)d_in[4];
    float* out = (float*)d_out;

    float *pq, *pk, *pv;
    cudaGetSymbolAddress((void**)&pq, g_q);
    cudaGetSymbolAddress((void**)&pk, g_k);
    cudaGetSymbolAddress((void**)&pv, g_v);
    __nv_bfloat16 *xh, *xl, *oh, *ol, *wh, *wl;
    cudaGetSymbolAddress((void**)&xh, g_x_hi);
    cudaGetSymbolAddress((void**)&xl, g_x_lo);
    cudaGetSymbolAddress((void**)&oh, g_o_hi);
    cudaGetSymbolAddress((void**)&ol, g_o_lo);
    cudaGetSymbolAddress((void**)&wh, g_w_hi);
    cudaGetSymbolAddress((void**)&wl, g_w_lo);

    cudaFuncSetAttribute(attn_kernel, cudaFuncAttributeMaxDynamicSharedMemorySize,
                         ATTN_SMEM_BYTES);
    cudaFuncSetAttribute(gemm_tc, cudaFuncAttributeMaxDynamicSharedMemorySize,
                         GEMM_SMEM);

    const int WELEM = DIM * DIM;

    // 0: split x
    split_kernel<<<(S_LEN * DIM / 4 + 255) / 256, 256>>>(x, xh, xl, S_LEN * DIM / 4);
    // 1-2: split weights (2 per launch)
    dim3 gw(WELEM / 4 / 256, 2);
    split2_kernel<<<gw, 256>>>(Wq, Wk, wh + 0 * WELEM, wl + 0 * WELEM,
                               wh + 1 * WELEM, wl + 1 * WELEM, WELEM / 4);
    split2_kernel<<<gw, 256>>>(Wv, Wo, wh + 2 * WELEM, wl + 2 * WELEM,
                               wh + 3 * WELEM, wl + 3 * WELEM, WELEM / 4);

    // 3: QKV projections + fused RoPE on q,k
    dim3 g_qkv(DIM / GBN, S_LEN / GBM, 3);
    gemm_tc<<<g_qkv, 256, GEMM_SMEM>>>(xh, xl, wh, wl, pq, pk, pv, 0x3);

    // 4: sliding-window attention (writes bf16 hi/lo O directly)
    dim3 g_att(S_LEN / AQ, NH);
    attn_kernel<<<g_att, 256, ATTN_SMEM_BYTES>>>();

    // 5: output projection (profiled launch under ncu -s 5 -c 1)
    dim3 g_out(DIM / GBN, S_LEN / GBM, 1);
    gemm_tc<<<g_out, 256, GEMM_SMEM>>>(oh, ol, wh + 3 * WELEM, wl + 3 * WELEM,
                                       out, out, out, 0);
}

// round 7
// speedup vs baseline: 2.9309x; 1.4105x over previous
#include <cuda_runtime.h>
#include <cuda_bf16.h>
#include <math.h>
#include <stdint.h>

#define S_LEN 8192
#define DIM   1024
#define NH    16
#define HD    64
#define WIN   512

// ---------------------------------------------------------------------------
// Device scratch
// ---------------------------------------------------------------------------
__device__ __nv_bfloat16 g_x_hi[S_LEN * DIM];
__device__ __nv_bfloat16 g_x_lo[S_LEN * DIM];
__device__ __nv_bfloat16 g_q_hi[S_LEN * DIM];
__device__ __nv_bfloat16 g_q_lo[S_LEN * DIM];
__device__ __nv_bfloat16 g_k_hi[S_LEN * DIM];
__device__ __nv_bfloat16 g_k_lo[S_LEN * DIM];
__device__ __nv_bfloat16 g_v_hi[S_LEN * DIM];
__device__ __nv_bfloat16 g_v_lo[S_LEN * DIM];
__device__ __nv_bfloat16 g_o_hi[S_LEN * DIM];
__device__ __nv_bfloat16 g_o_lo[S_LEN * DIM];
__device__ __nv_bfloat16 g_w_hi[4 * DIM * DIM];
__device__ __nv_bfloat16 g_w_lo[4 * DIM * DIM];

// ---------------------------------------------------------------------------
// PTX helpers
// ---------------------------------------------------------------------------
__device__ __forceinline__ uint32_t smem_u32(const void* p) {
    uint32_t a;
    asm("{ .reg .u64 t; cvta.to.shared.u64 t, %1; cvt.u32.u64 %0, t; }"
        : "=r"(a) : "l"(p));
    return a;
}
__device__ __forceinline__ void cp_async16(uint32_t dst, const void* src) {
    asm volatile("cp.async.cg.shared.global [%0], [%1], 16;"
                 :: "r"(dst), "l"(src) : "memory");
}
__device__ __forceinline__ void cp_commit() {
    asm volatile("cp.async.commit_group;" ::: "memory");
}
__device__ __forceinline__ void cp_wait0() {
    asm volatile("cp.async.wait_group 0;" ::: "memory");
}
__device__ __forceinline__ void ldmx4(uint32_t* r, uint32_t addr) {
    asm volatile("ldmatrix.sync.aligned.m8n8.x4.shared.b16 {%0,%1,%2,%3}, [%4];"
                 : "=r"(r[0]), "=r"(r[1]), "=r"(r[2]), "=r"(r[3]) : "r"(addr));
}
__device__ __forceinline__ void ldmx4t(uint32_t* r, uint32_t addr) {
    asm volatile("ldmatrix.sync.aligned.m8n8.x4.trans.shared.b16 {%0,%1,%2,%3}, [%4];"
                 : "=r"(r[0]), "=r"(r[1]), "=r"(r[2]), "=r"(r[3]) : "r"(addr));
}
__device__ __forceinline__ void mma16816(float* d, const uint32_t* a, const uint32_t* b) {
    asm volatile(
        "mma.sync.aligned.m16n8k16.row.col.f32.bf16.bf16.f32 "
        "{%0,%1,%2,%3}, {%4,%5,%6,%7}, {%8,%9}, {%0,%1,%2,%3};"
        : "+f"(d[0]), "+f"(d[1]), "+f"(d[2]), "+f"(d[3])
        : "r"(a[0]), "r"(a[1]), "r"(a[2]), "r"(a[3]), "r"(b[0]), "r"(b[1]));
}

__device__ __forceinline__ uint32_t pack_bf16(float a, float b) {
    __nv_bfloat162 t = __floats2bfloat162_rn(a, b);
    return *(uint32_t*)&t;
}
// split (a,b) into bf16 hi/lo packs
__device__ __forceinline__ void split_pack(float a, float b, uint32_t& hp, uint32_t& lp) {
    __nv_bfloat16 ha = __float2bfloat16(a), hb = __float2bfloat16(b);
    float la = a - __bfloat162float(ha);
    float lb = b - __bfloat162float(hb);
    __nv_bfloat162 h2; h2.x = ha; h2.y = hb;
    hp = *(uint32_t*)&h2;
    lp = pack_bf16(la, lb);
}

// FMA-pipe exp2 (no MUFU). x must be <= 0; clamped at -126.
__device__ __forceinline__ float exp2_fast(float x) {
    x = fmaxf(x, -126.f);
    float z = x + 12582912.f;                  // 1.5*2^23: round-to-int
    int n_i = __float_as_int(z) - 0x4B400000;
    float n = z - 12582912.f;
    float f = x - n;                           // [-0.5, 0.5]
    float p = 0.0096181291f;
    p = fmaf(p, f, 0.0555041087f);
    p = fmaf(p, f, 0.2402265069f);
    p = fmaf(p, f, 0.6931471806f);
    p = fmaf(p, f, 1.0f);
    return p * __int_as_float((n_i + 127) << 23);
}

// ---------------------------------------------------------------------------
// fp32 -> bf16 hi/lo splits
// ---------------------------------------------------------------------------
__device__ __forceinline__ void split4(const float* vv, uint2& h2, uint2& l2) {
    __nv_bfloat16 h[4], l[4];
#pragma unroll
    for (int j = 0; j < 4; j++) {
        h[j] = __float2bfloat16(vv[j]);
        l[j] = __float2bfloat16(vv[j] - __bfloat162float(h[j]));
    }
    h2 = *(uint2*)h;
    l2 = *(uint2*)l;
}

__global__ void split_kernel(const float* __restrict__ src,
                             __nv_bfloat16* __restrict__ hi,
                             __nv_bfloat16* __restrict__ lo, int n4) {
    int i = blockIdx.x * blockDim.x + threadIdx.x;
    if (i >= n4) return;
    float4 v = ((const float4*)src)[i];
    float vv[4] = {v.x, v.y, v.z, v.w};
    uint2 h2, l2;
    split4(vv, h2, l2);
    ((uint2*)hi)[i] = h2;
    ((uint2*)lo)[i] = l2;
}

__global__ void split2_kernel(const float* __restrict__ s0, const float* __restrict__ s1,
                              __nv_bfloat16* __restrict__ h0, __nv_bfloat16* __restrict__ l0,
                              __nv_bfloat16* __restrict__ h1, __nv_bfloat16* __restrict__ l1,
                              int n4) {
    const float* s = blockIdx.y ? s1 : s0;
    __nv_bfloat16* hh = blockIdx.y ? h1 : h0;
    __nv_bfloat16* ll = blockIdx.y ? l1 : l0;
    int i = blockIdx.x * blockDim.x + threadIdx.x;
    if (i >= n4) return;
    float4 v = ((const float4*)s)[i];
    float vv[4] = {v.x, v.y, v.z, v.w};
    uint2 h2, l2;
    split4(vv, h2, l2);
    ((uint2*)hh)[i] = h2;
    ((uint2*)ll)[i] = l2;
}

// ---------------------------------------------------------------------------
// Split-bf16 GEMM via mma.sync (NT).  BF16OUT: write bf16 hi/lo (+rope);
// else write fp32 C.
// ---------------------------------------------------------------------------
#define GBM 128
#define GBN 128
#define GBK 32
#define NCHUNK (DIM / GBK)
#define LDSW 40
#define TILE_B (128 * LDSW * 2)
#define STAGE_B (4 * TILE_B)
#define GEMM_SMEM (2 * STAGE_B)

template<bool BF16OUT>
__global__ void __launch_bounds__(256, 2) gemm_tc(
    const __nv_bfloat16* __restrict__ A_hi, const __nv_bfloat16* __restrict__ A_lo,
    const __nv_bfloat16* __restrict__ W_hi, const __nv_bfloat16* __restrict__ W_lo,
    float* __restrict__ Cf,
    __nv_bfloat16* __restrict__ H0, __nv_bfloat16* __restrict__ L0,
    __nv_bfloat16* __restrict__ H1, __nv_bfloat16* __restrict__ L1,
    __nv_bfloat16* __restrict__ H2, __nv_bfloat16* __restrict__ L2,
    int rope_mask)
{
    extern __shared__ char smem[];
    const int tid  = threadIdx.x;
    const int lane = tid & 31;
    const int wid  = tid >> 5;
    const int wm   = wid & 3;
    const int wn   = wid >> 2;
    const int z = blockIdx.z;
    const int m0 = blockIdx.y * GBM;
    const int n0 = blockIdx.x * GBN;
    const bool rope = (rope_mask >> z) & 1;
    const __nv_bfloat16* Bh = W_hi + (size_t)z * DIM * DIM;
    const __nv_bfloat16* Bl = W_lo + (size_t)z * DIM * DIM;
    __nv_bfloat16* Hc = (z == 0) ? H0 : (z == 1) ? H1 : H2;
    __nv_bfloat16* Lc = (z == 0) ? L0 : (z == 1) ? L1 : L2;

    const uint32_t sbase = smem_u32(smem);

    auto prefetch = [&](int st, int k0) {
        uint32_t stage = sbase + st * STAGE_B;
#pragma unroll
        for (int half = 0; half < 2; half++) {
            int u = tid + half * 256;
            int row = u >> 2;
            int ch  = u & 3;
            uint32_t doff = row * (LDSW * 2) + ch * 16;
            size_t aoff = (size_t)(m0 + row) * DIM + k0 + ch * 8;
            size_t boff = (size_t)(n0 + row) * DIM + k0 + ch * 8;
            cp_async16(stage + 0 * TILE_B + doff, A_hi + aoff);
            cp_async16(stage + 1 * TILE_B + doff, A_lo + aoff);
            cp_async16(stage + 2 * TILE_B + doff, Bh + boff);
            cp_async16(stage + 3 * TILE_B + doff, Bl + boff);
        }
        cp_commit();
    };

    float acc[2][8][4];
#pragma unroll
    for (int mt = 0; mt < 2; mt++)
#pragma unroll
        for (int nt = 0; nt < 8; nt++)
#pragma unroll
            for (int r = 0; r < 4; r++) acc[mt][nt][r] = 0.f;

    prefetch(0, 0);

    for (int c = 0; c < NCHUNK; c++) {
        cp_wait0();
        __syncthreads();
        if (c + 1 < NCHUNK) prefetch((c + 1) & 1, (c + 1) * GBK);

        uint32_t stage = sbase + (c & 1) * STAGE_B;
        uint32_t sAh = stage + 0 * TILE_B;
        uint32_t sAl = stage + 1 * TILE_B;
        uint32_t sBh = stage + 2 * TILE_B;
        uint32_t sBl = stage + 3 * TILE_B;

#pragma unroll
        for (int ks = 0; ks < 2; ks++) {
            uint32_t ah[2][4], al[2][4];
#pragma unroll
            for (int mt = 0; mt < 2; mt++) {
                uint32_t roff = (wm * 32 + mt * 16 + (lane & 15)) * (LDSW * 2)
                              + (ks * 16 + (lane >> 4) * 8) * 2;
                ldmx4(ah[mt], sAh + roff);
                ldmx4(al[mt], sAl + roff);
            }
#pragma unroll
            for (int p = 0; p < 4; p++) {
                int nloc = wn * 64 + p * 16 + (lane & 7) + ((lane >> 4) << 3);
                uint32_t roff = nloc * (LDSW * 2)
                              + (ks * 16 + ((lane >> 3) & 1) * 8) * 2;
                uint32_t bh[2][2], bl[2][2], r4[4];
                ldmx4(r4, sBh + roff);
                bh[0][0] = r4[0]; bh[0][1] = r4[1];
                bh[1][0] = r4[2]; bh[1][1] = r4[3];
                ldmx4(r4, sBl + roff);
                bl[0][0] = r4[0]; bl[0][1] = r4[1];
                bl[1][0] = r4[2]; bl[1][1] = r4[3];
#pragma unroll
                for (int mt = 0; mt < 2; mt++)
#pragma unroll
                    for (int e = 0; e < 2; e++) {
                        float* a4 = acc[mt][2 * p + e];
                        mma16816(a4, ah[mt], bh[e]);
                        mma16816(a4, ah[mt], bl[e]);
                        mma16816(a4, al[mt], bh[e]);
                    }
            }
        }
    }

#pragma unroll
    for (int mt = 0; mt < 2; mt++) {
#pragma unroll
        for (int nt = 0; nt < 8; nt++) {
            int col = n0 + wn * 64 + nt * 8 + 2 * (lane & 3);
            int r_lo = m0 + wm * 32 + mt * 16 + (lane >> 2);
            int r_hi = r_lo + 8;
            float* a4 = acc[mt][nt];
            if (rope) {
                int d = col & (HD - 1);
                float inv = powf(10000.f, -(float)d / (float)HD);
                float sv, cv;
                sincosf((float)r_lo * inv, &sv, &cv);
                float x1 = a4[0], x2 = a4[1];
                a4[0] = x1 * cv - x2 * sv;
                a4[1] = x1 * sv + x2 * cv;
                sincosf((float)r_hi * inv, &sv, &cv);
                x1 = a4[2]; x2 = a4[3];
                a4[2] = x1 * cv - x2 * sv;
                a4[3] = x1 * sv + x2 * cv;
            }
            if (BF16OUT) {
                uint32_t hp, lp;
                split_pack(a4[0], a4[1], hp, lp);
                *(uint32_t*)&Hc[(size_t)r_lo * DIM + col] = hp;
                *(uint32_t*)&Lc[(size_t)r_lo * DIM + col] = lp;
                split_pack(a4[2], a4[3], hp, lp);
                *(uint32_t*)&Hc[(size_t)r_hi * DIM + col] = hp;
                *(uint32_t*)&Lc[(size_t)r_hi * DIM + col] = lp;
            } else {
                *(float2*)(Cf + (size_t)r_lo * DIM + col) = make_float2(a4[0], a4[1]);
                *(float2*)(Cf + (size_t)r_hi * DIM + col) = make_float2(a4[2], a4[3]);
            }
        }
    }
}

// ---------------------------------------------------------------------------
// Sliding-window attention via mma.sync (split-bf16), FMA-pipe exp2 softmax.
// CTA = 128 queries x 1 head; 8 warps, each 16q x full 64-key tile.
// ---------------------------------------------------------------------------
#define AQT 128
#define AKT 64
#define QSTR 144   // bytes per 64-bf16 row (+16B pad; ldmatrix conflict-free)
#define AQ_B (AQT * QSTR)          // 18432 per array
#define AK_B (AKT * QSTR)          // 9216 per array
#define ASTG_B (4 * AK_B)          // kh, kl, vh, vl = 36864
#define ATT_SMEM (2 * AQ_B + 2 * ASTG_B)   // 110592

__global__ void __launch_bounds__(256) attn_kernel()
{
    extern __shared__ char smem[];
    const int tid  = threadIdx.x;
    const int lane = tid & 31;
    const int wid  = tid >> 5;
    const int q0 = blockIdx.x * AQT;
    const int h  = blockIdx.y;

    const uint32_t sb = smem_u32(smem);
    const uint32_t QH = sb;
    const uint32_t QL = sb + AQ_B;
    const uint32_t STG = sb + 2 * AQ_B;

    const int gk_start = (q0 - WIN > 0) ? (q0 - WIN) : 0;
    const int ntiles = (q0 + AQT - gk_start) / AKT;

    // Q tiles (hi, lo) via cp.async
#pragma unroll
    for (int it = 0; it < 4; it++) {
        int u = tid + it * 256;        // 0..1023
        int row = u >> 3, ch = u & 7;
        size_t goff = (size_t)(q0 + row) * DIM + h * HD + ch * 8;
        cp_async16(QH + row * QSTR + ch * 16, g_q_hi + goff);
        cp_async16(QL + row * QSTR + ch * 16, g_q_lo + goff);
    }
    auto load_kv = [&](int st, int kb) {
        uint32_t s = STG + st * ASTG_B;
#pragma unroll
        for (int it = 0; it < 2; it++) {
            int u = tid + it * 256;    // 0..511
            int row = u >> 3, ch = u & 7;
            uint32_t doff = row * QSTR + ch * 16;
            size_t goff = (size_t)(kb + row) * DIM + h * HD + ch * 8;
            cp_async16(s + 0 * AK_B + doff, g_k_hi + goff);
            cp_async16(s + 1 * AK_B + doff, g_k_lo + goff);
            cp_async16(s + 2 * AK_B + doff, g_v_hi + goff);
            cp_async16(s + 3 * AK_B + doff, g_v_lo + goff);
        }
        cp_commit();
    };
    load_kv(0, gk_start);

    const int r0 = q0 + wid * 16 + (lane >> 2);
    const int r1 = r0 + 8;
    float m0v = -1e30f, m1v = -1e30f, l0v = 0.f, l1v = 0.f;
    float o[8][4];
#pragma unroll
    for (int nt = 0; nt < 8; nt++)
#pragma unroll
        for (int j = 0; j < 4; j++) o[nt][j] = 0.f;

    const float CSC = 0.125f * 1.44269504f;   // scale * log2(e)

    for (int t = 0; t < ntiles; t++) {
        cp_wait0();
        __syncthreads();
        if (t + 1 < ntiles) load_kv((t + 1) & 1, gk_start + (t + 1) * AKT);

        uint32_t stg = STG + (t & 1) * ASTG_B;
        uint32_t sKH = stg + 0 * AK_B;
        uint32_t sKL = stg + 1 * AK_B;
        uint32_t sVH = stg + 2 * AK_B;
        uint32_t sVL = stg + 3 * AK_B;

        // ---- S = Q K^T (split-bf16, 3 combos) ----
        float sacc[8][4];
#pragma unroll
        for (int nt = 0; nt < 8; nt++)
#pragma unroll
            for (int j = 0; j < 4; j++) sacc[nt][j] = 0.f;

#pragma unroll
        for (int ks = 0; ks < 4; ks++) {
            uint32_t aqh[4], aql[4];
            uint32_t qoff = (wid * 16 + (lane & 15)) * QSTR
                          + (ks * 16 + (lane >> 4) * 8) * 2;
            ldmx4(aqh, QH + qoff);
            ldmx4(aql, QL + qoff);
#pragma unroll
            for (int p = 0; p < 4; p++) {
                int nloc = p * 16 + (lane & 7) + ((lane >> 4) << 3);
                uint32_t roff = nloc * QSTR + (ks * 16 + ((lane >> 3) & 1) * 8) * 2;
                uint32_t bh[2][2], bl[2][2], r4[4];
                ldmx4(r4, sKH + roff);
                bh[0][0] = r4[0]; bh[0][1] = r4[1];
                bh[1][0] = r4[2]; bh[1][1] = r4[3];
                ldmx4(r4, sKL + roff);
                bl[0][0] = r4[0]; bl[0][1] = r4[1];
                bl[1][0] = r4[2]; bl[1][1] = r4[3];
#pragma unroll
                for (int e = 0; e < 2; e++) {
                    float* a4 = sacc[2 * p + e];
                    mma16816(a4, aqh, bh[e]);
                    mma16816(a4, aqh, bl[e]);
                    mma16816(a4, aql, bh[e]);
                }
            }
        }

        // ---- masked online softmax (log2 domain, FMA-pipe exp2) ----
        const int kb = gk_start + t * AKT;
        float mt0 = -1e30f, mt1 = -1e30f;
#pragma unroll
        for (int nt = 0; nt < 8; nt++) {
            int cb = kb + nt * 8 + 2 * (lane & 3);
#pragma unroll
            for (int j = 0; j < 4; j++) {
                int kidx = cb + (j & 1);
                int r = (j < 2) ? r0 : r1;
                bool ok = (kidx <= r) && (kidx >= r - (WIN - 1));
                float val = ok ? sacc[nt][j] * CSC : -1e30f;
                sacc[nt][j] = val;
                if (j < 2) mt0 = fmaxf(mt0, val);
                else       mt1 = fmaxf(mt1, val);
            }
        }
        mt0 = fmaxf(mt0, __shfl_xor_sync(0xffffffffu, mt0, 1));
        mt0 = fmaxf(mt0, __shfl_xor_sync(0xffffffffu, mt0, 2));
        mt1 = fmaxf(mt1, __shfl_xor_sync(0xffffffffu, mt1, 1));
        mt1 = fmaxf(mt1, __shfl_xor_sync(0xffffffffu, mt1, 2));
        float mn0 = fmaxf(m0v, mt0), mn1 = fmaxf(m1v, mt1);
        float al0 = exp2_fast(m0v - mn0), al1 = exp2_fast(m1v - mn1);
        m0v = mn0; m1v = mn1;
        float ls0 = 0.f, ls1 = 0.f;
#pragma unroll
        for (int nt = 0; nt < 8; nt++) {
            float p0 = exp2_fast(sacc[nt][0] - mn0);
            float p1 = exp2_fast(sacc[nt][1] - mn0);
            float p2 = exp2_fast(sacc[nt][2] - mn1);
            float p3 = exp2_fast(sacc[nt][3] - mn1);
            sacc[nt][0] = p0; sacc[nt][1] = p1;
            sacc[nt][2] = p2; sacc[nt][3] = p3;
            ls0 += p0 + p1; ls1 += p2 + p3;
        }
        ls0 += __shfl_xor_sync(0xffffffffu, ls0, 1);
        ls0 += __shfl_xor_sync(0xffffffffu, ls0, 2);
        ls1 += __shfl_xor_sync(0xffffffffu, ls1, 1);
        ls1 += __shfl_xor_sync(0xffffffffu, ls1, 2);
        l0v = l0v * al0 + ls0;
        l1v = l1v * al1 + ls1;
#pragma unroll
        for (int nt = 0; nt < 8; nt++) {
            o[nt][0] *= al0; o[nt][1] *= al0;
            o[nt][2] *= al1; o[nt][3] *= al1;
        }

        // ---- O += P V  (P hi/lo from C-frags; V via ldmatrix.trans) ----
#pragma unroll
        for (int ks = 0; ks < 4; ks++) {
            uint32_t aph[4], apl[4];
            split_pack(sacc[2 * ks][0], sacc[2 * ks][1], aph[0], apl[0]);
            split_pack(sacc[2 * ks][2], sacc[2 * ks][3], aph[1], apl[1]);
            split_pack(sacc[2 * ks + 1][0], sacc[2 * ks + 1][1], aph[2], apl[2]);
            split_pack(sacc[2 * ks + 1][2], sacc[2 * ks + 1][3], aph[3], apl[3]);
#pragma unroll
            for (int p = 0; p < 4; p++) {
                uint32_t voff = (ks * 16 + (lane & 15)) * QSTR
                              + (p * 16 + 8 * (lane >> 4)) * 2;
                uint32_t bvh[2][2], bvl[2][2], r4[4];
                ldmx4t(r4, sVH + voff);
                bvh[0][0] = r4[0]; bvh[0][1] = r4[1];
                bvh[1][0] = r4[2]; bvh[1][1] = r4[3];
                ldmx4t(r4, sVL + voff);
                bvl[0][0] = r4[0]; bvl[0][1] = r4[1];
                bvl[1][0] = r4[2]; bvl[1][1] = r4[3];
#pragma unroll
                for (int e = 0; e < 2; e++) {
                    float* o4 = o[2 * p + e];
                    mma16816(o4, aph, bvh[e]);
                    mma16816(o4, aph, bvl[e]);
                    mma16816(o4, apl, bvh[e]);
                }
            }
        }
    }

    // ---- normalize + write bf16 hi/lo ----
    float li0 = 1.f / l0v, li1 = 1.f / l1v;
#pragma unroll
    for (int nt = 0; nt < 8; nt++) {
        int d0 = nt * 8 + 2 * (lane & 3);
        uint32_t hp, lp;
        split_pack(o[nt][0] * li0, o[nt][1] * li0, hp, lp);
        size_t off0 = (size_t)r0 * DIM + h * HD + d0;
        *(uint32_t*)&g_o_hi[off0] = hp;
        *(uint32_t*)&g_o_lo[off0] = lp;
        split_pack(o[nt][2] * li1, o[nt][3] * li1, hp, lp);
        size_t off1 = (size_t)r1 * DIM + h * HD + d0;
        *(uint32_t*)&g_o_hi[off1] = hp;
        *(uint32_t*)&g_o_lo[off1] = lp;
    }
}

// ---------------------------------------------------------------------------
extern "C" void kernel_launch(void* const* d_in, const int* in_sizes, int n_in,
                              void* d_out, int out_size)
{
    const float* x  = (const float*)d_in[0];
    const float* Wq = (const float*)d_in[1];
    const float* Wk = (const float*)d_in[2];
    const float* Wv = (const float*)d_in[3];
    const float* Wo = (const float*)d_in[4];
    float* out = (float*)d_out;

    __nv_bfloat16 *xh, *xl, *qh, *ql, *kh, *kl, *vh, *vl, *oh, *ol, *wh, *wl;
    cudaGetSymbolAddress((void**)&xh, g_x_hi);
    cudaGetSymbolAddress((void**)&xl, g_x_lo);
    cudaGetSymbolAddress((void**)&qh, g_q_hi);
    cudaGetSymbolAddress((void**)&ql, g_q_lo);
    cudaGetSymbolAddress((void**)&kh, g_k_hi);
    cudaGetSymbolAddress((void**)&kl, g_k_lo);
    cudaGetSymbolAddress((void**)&vh, g_v_hi);
    cudaGetSymbolAddress((void**)&vl, g_v_lo);
    cudaGetSymbolAddress((void**)&oh, g_o_hi);
    cudaGetSymbolAddress((void**)&ol, g_o_lo);
    cudaGetSymbolAddress((void**)&wh, g_w_hi);
    cudaGetSymbolAddress((void**)&wl, g_w_lo);

    cudaFuncSetAttribute(attn_kernel, cudaFuncAttributeMaxDynamicSharedMemorySize,
                         ATT_SMEM);
    cudaFuncSetAttribute(gemm_tc<true>, cudaFuncAttributeMaxDynamicSharedMemorySize,
                         GEMM_SMEM);
    cudaFuncSetAttribute(gemm_tc<false>, cudaFuncAttributeMaxDynamicSharedMemorySize,
                         GEMM_SMEM);

    const int WELEM = DIM * DIM;

    // 0: split x
    split_kernel<<<(S_LEN * DIM / 4 + 255) / 256, 256>>>(x, xh, xl, S_LEN * DIM / 4);
    // 1-2: split weights
    dim3 gw(WELEM / 4 / 256, 2);
    split2_kernel<<<gw, 256>>>(Wq, Wk, wh + 0 * WELEM, wl + 0 * WELEM,
                               wh + 1 * WELEM, wl + 1 * WELEM, WELEM / 4);
    split2_kernel<<<gw, 256>>>(Wv, Wo, wh + 2 * WELEM, wl + 2 * WELEM,
                               wh + 3 * WELEM, wl + 3 * WELEM, WELEM / 4);

    // 3: QKV projections + RoPE, bf16 hi/lo outputs
    dim3 g_qkv(DIM / GBN, S_LEN / GBM, 3);
    gemm_tc<true><<<g_qkv, 256, GEMM_SMEM>>>(xh, xl, wh, wl, nullptr,
                                             qh, ql, kh, kl, vh, vl, 0x3);

    // 4: attention (tensor-core, split-bf16)
    dim3 g_att(S_LEN / AQT, NH);
    attn_kernel<<<g_att, 256, ATT_SMEM>>>();

    // 5: output projection (fp32 out)
    dim3 g_out(DIM / GBN, S_LEN / GBM, 1);
    gemm_tc<false><<<g_out, 256, GEMM_SMEM>>>(oh, ol, wh + 3 * WELEM, wl + 3 * WELEM,
                                              out, nullptr, nullptr, nullptr,
                                              nullptr, nullptr, nullptr, 0);
}